// round 6
// baseline (speedup 1.0000x reference)
#include <cuda_runtime.h>
#include <math.h>

#define NB 4
#define NPTS 4096
#define KNN 16
#define DPf 64
#define DMf 128
#define M1 (NB*NPTS)          /* 16384  */
#define M2 (M1*KNN)           /* 262144 */
#define EPSV 1e-8f
#define PITCH 132             /* smem tile pitch; 4*132=528 words, %32=16 -> conflict-free */
#define BROWS 64

// ---------------- scratch ----------------
__device__ float g_x [(size_t)M1*DMf];
__device__ float g_q [(size_t)M1*DMf];
__device__ float g_kf[(size_t)M1*DMf];
__device__ float g_vf[(size_t)M1*DMf];
__device__ int   g_idx[M1*KNN];
__device__ float g_logits[(size_t)M2*DMf];
__device__ float g_pe    [(size_t)M2*DMf];

// ---------------- packed f32x2 helpers ----------------
__device__ __forceinline__ unsigned long long pack2(float x, float y) {
    unsigned long long r;
    asm("mov.b64 %0, {%1, %2};" : "=l"(r) : "f"(x), "f"(y));
    return r;
}
__device__ __forceinline__ float2 unpack2(unsigned long long v) {
    float2 f;
    asm("mov.b64 {%0, %1}, %2;" : "=f"(f.x), "=f"(f.y) : "l"(v));
    return f;
}
__device__ __forceinline__ void ffma2(unsigned long long& d,
                                      unsigned long long a,
                                      unsigned long long b) {
    asm("fma.rn.f32x2 %0, %1, %2, %0;" : "+l"(d) : "l"(a), "l"(b));
}

// ---------------- cp.async helpers ----------------
__device__ __forceinline__ unsigned smem_u32(const void* p) {
    unsigned a;
    asm("{ .reg .u64 t; cvta.to.shared.u64 t, %1; cvt.u32.u64 %0, t; }" : "=r"(a) : "l"(p));
    return a;
}
__device__ __forceinline__ void cpa16(unsigned dst, const void* src) {
    asm volatile("cp.async.ca.shared.global [%0], [%1], 16;" :: "r"(dst), "l"(src));
}
__device__ __forceinline__ void cpa_commit() { asm volatile("cp.async.commit_group;"); }
template<int N> __device__ __forceinline__ void cpa_wait() {
    asm volatile("cp.async.wait_group %0;" :: "n"(N));
}

// ---------------- KNN ----------------
__global__ void knn_kernel(const float* __restrict__ xyz) {
    int warp = threadIdx.x >> 5;
    int lane = threadIdx.x & 31;
    int row  = blockIdx.x * 4 + warp;
    int b = row >> 12;
    int n = row & (NPTS - 1);
    const float* xb = xyz + (size_t)b * NPTS * 3;
    float qx = xb[n*3+0], qy = xb[n*3+1], qz = xb[n*3+2];
    float sq = qx*qx + qy*qy + qz*qz;

    unsigned long long best[16];
#pragma unroll
    for (int i = 0; i < 16; i++) best[i] = ~0ULL;

    for (int t = 0; t < NPTS/32; t++) {
        int j = t*32 + lane;
        float x = xb[j*3+0], y = xb[j*3+1], z = xb[j*3+2];
        float sj = x*x + y*y + z*z;
        float d = sq + sj - 2.0f*(qx*x + qy*y + qz*z);
        unsigned u = __float_as_uint(d);
        u = (u & 0x80000000u) ? ~u : (u | 0x80000000u);
        unsigned long long key = ((unsigned long long)u << 32) | (unsigned)j;
        if (key < best[15]) {
            int p = 15;
            while (p > 0 && best[p-1] > key) { best[p] = best[p-1]; p--; }
            best[p] = key;
        }
    }

    __shared__ unsigned long long sh[4][512];
#pragma unroll
    for (int i = 0; i < 16; i++) sh[warp][lane*16 + i] = best[i];
    __syncwarp();

    int p = 0;
    for (int r = 0; r < 16; r++) {
        unsigned long long v = (p < 16) ? sh[warp][lane*16 + p] : ~0ULL;
        unsigned long long m = v;
#pragma unroll
        for (int off = 16; off; off >>= 1) {
            unsigned long long o = __shfl_xor_sync(0xffffffffu, m, off);
            m = (o < m) ? o : m;
        }
        if (v == m) { g_idx[row*KNN + r] = (int)(m & 0xffffffffu); p++; }
        __syncwarp();
    }
}

// ---------------- small fp32 GEMM (fc1, qkv) ----------------
__global__ void __launch_bounds__(256, 2)
gemm_small(const float* __restrict__ A, int lda, int Ka,
           const float* __restrict__ W,
           const float* __restrict__ bias,
           float* __restrict__ C,
           const float* W2, float* C2, const float* W3, float* C3) {
    __shared__ float As[32][132];
    __shared__ float Ws[32][128];

    if (gridDim.y == 3) {
        if (blockIdx.y == 1) { W = W2; C = C2; }
        else if (blockIdx.y == 2) { W = W3; C = C3; }
    }

    int bm  = blockIdx.x * 128;
    int tid = threadIdx.x;
    int tm  = tid >> 4, tn = tid & 15;

    unsigned long long acc[8][4];
#pragma unroll
    for (int i = 0; i < 8; i++)
#pragma unroll
        for (int j = 0; j < 4; j++) acc[i][j] = 0ULL;

    for (int k0 = 0; k0 < Ka; k0 += 32) {
#pragma unroll
        for (int pss = 0; pss < 4; pss++) {
            int idx4 = pss*256 + tid;
            int r  = idx4 >> 3;
            int c4 = idx4 & 7;
            float4 v = *(const float4*)(A + (size_t)(bm + r)*lda + k0 + c4*4);
            As[c4*4+0][r] = v.x; As[c4*4+1][r] = v.y;
            As[c4*4+2][r] = v.z; As[c4*4+3][r] = v.w;
        }
#pragma unroll
        for (int pss = 0; pss < 4; pss++) {
            int idx4 = pss*256 + tid;
            int r  = idx4 >> 5;
            int c4 = idx4 & 31;
            *(float4*)&Ws[r][c4*4] = *(const float4*)(W + (size_t)(k0 + r)*128 + c4*4);
        }
        __syncthreads();
#pragma unroll
        for (int kk = 0; kk < 32; kk++) {
            float4 a0 = *(const float4*)&As[kk][tm*8];
            float4 a1 = *(const float4*)&As[kk][tm*8 + 4];
            unsigned long long bv[4];
            bv[0] = *(const unsigned long long*)&Ws[kk][tn*8];
            bv[1] = *(const unsigned long long*)&Ws[kk][tn*8+2];
            bv[2] = *(const unsigned long long*)&Ws[kk][tn*8+4];
            bv[3] = *(const unsigned long long*)&Ws[kk][tn*8+6];
            unsigned long long av[8] = { pack2(a0.x, a0.x), pack2(a0.y, a0.y),
                                         pack2(a0.z, a0.z), pack2(a0.w, a0.w),
                                         pack2(a1.x, a1.x), pack2(a1.y, a1.y),
                                         pack2(a1.z, a1.z), pack2(a1.w, a1.w) };
#pragma unroll
            for (int i = 0; i < 8; i++)
#pragma unroll
                for (int j = 0; j < 4; j++) ffma2(acc[i][j], av[i], bv[j]);
        }
        __syncthreads();
    }

    float bia[8];
#pragma unroll
    for (int j = 0; j < 8; j++) bia[j] = bias ? bias[tn*8 + j] : 0.0f;

#pragma unroll
    for (int i = 0; i < 8; i++) {
        size_t row = (size_t)bm + tm*8 + i;
        float v[8];
#pragma unroll
        for (int j = 0; j < 4; j++) {
            float2 f = unpack2(acc[i][j]);
            v[2*j]   = f.x + bia[2*j];
            v[2*j+1] = f.y + bia[2*j+1];
        }
        float4* cp = (float4*)(C + row*128 + tn*8);
        cp[0] = make_float4(v[0], v[1], v[2], v[3]);
        cp[1] = make_float4(v[4], v[5], v[6], v[7]);
    }
}

// ---------------- fused mega-kernel: gather/sim/h1/qk + 4-GEMM chain ----------------
// SMEM float offsets
#define OFF_AS  0
#define OFF_BS  (BROWS*PITCH)                   /* 8448 */
#define OFF_W   (2*BROWS*PITCH)                 /* 16896; 2 x 32x128 quarters */
#define OFF_QS  (OFF_W + 2*32*128)              /* 25088; 4x128 q rows */
#define OFF_SIM (OFF_QS + 512)                  /* 25600; 64 */
#define OFF_QN  (OFF_SIM + 64)                  /* 25664; 4 */
#define OFF_IDX (OFF_QN + 4)                    /* 25668; 64 ints */
#define FUSED_FLOATS (OFF_IDX + 64)             /* 25732 -> 102928 B */

__device__ __forceinline__ void loadq32(unsigned sW, const float* __restrict__ W,
                                        int quarter, int tid) {
    const float* src = W + (size_t)quarter*32*128;
#pragma unroll
    for (int it = 0; it < 4; it++) {
        int c = it*256 + tid;                  // 1024 float4
        cpa16(sW + (unsigned)c*16u, src + c*4);
    }
}

// 32-k-step microkernel: acc(4x4 f32x2) += T[4 rows] x Wq[32x128]
__device__ __forceinline__ void mm32(const float* __restrict__ T, int kbase,
                                     const float* __restrict__ Wq,
                                     int tm, int tn, unsigned long long acc[4][4]) {
    const float* ap  = T + tm*4*PITCH + kbase;
    const float* wp  = Wq + tn*4;
    const float* wp2 = Wq + 64 + tn*4;
#pragma unroll 4
    for (int kk = 0; kk < 32; kk++) {
        unsigned long long b0 = *(const unsigned long long*)(wp  + kk*128);
        unsigned long long b1 = *(const unsigned long long*)(wp  + kk*128 + 2);
        unsigned long long b2 = *(const unsigned long long*)(wp2 + kk*128);
        unsigned long long b3 = *(const unsigned long long*)(wp2 + kk*128 + 2);
#pragma unroll
        for (int i = 0; i < 4; i++) {
            float a = ap[i*PITCH + kk];
            unsigned long long av = pack2(a, a);
            ffma2(acc[i][0], av, b0);
            ffma2(acc[i][1], av, b1);
            ffma2(acc[i][2], av, b2);
            ffma2(acc[i][3], av, b3);
        }
    }
}

__global__ void __launch_bounds__(256, 2)
fused_chain(const float* __restrict__ xyz,
            const float* __restrict__ d1_w, const float* __restrict__ d1_b,
            const float* __restrict__ d2_w, const float* __restrict__ d2_b,
            const float* __restrict__ sim_w, const float* __restrict__ sim_b,
            const float* __restrict__ g1_w, const float* __restrict__ g1_b,
            const float* __restrict__ g2_w, const float* __restrict__ g2_b) {
    extern __shared__ float sm[];
    float* As   = sm + OFF_AS;
    float* Bs   = sm + OFF_BS;
    float* Wb   = sm + OFF_W;
    float* Qs   = sm + OFF_QS;
    float* ssim = sm + OFF_SIM;
    float* sqn  = sm + OFF_QN;
    int*   sidx = (int*)(sm + OFF_IDX);
    unsigned sW = smem_u32(Wb);

    int tid  = threadIdx.x;
    int wid  = tid >> 5, lane = tid & 31;
    int tm   = tid >> 4, tn = tid & 15;
    int m0   = blockIdx.x * 4;                 // 4 query rows
    size_t bm = (size_t)blockIdx.x * BROWS;    // 64 M2 rows
    int b    = m0 >> 12;

    // kick off weight chunk 0 ASAP (overlaps gather prologue)
    loadq32(sW, d2_w, 0, tid);
    cpa_commit();

    // ---- prologue: load q rows + idx ----
    if (tid < 64) sidx[tid] = g_idx[m0*KNN + tid];
    {   // 512 floats of q
        float2 v = *(const float2*)(g_q + (size_t)m0*DMf + tid*2);
        *(float2*)(Qs + tid*2) = v;
    }
    __syncthreads();

    // q norms (warps 0-3)
    if (wid < 4) {
        float4 qf = *(const float4*)(Qs + wid*128 + lane*4);
        float s = qf.x*qf.x + qf.y*qf.y + qf.z*qf.z + qf.w*qf.w;
#pragma unroll
        for (int off = 16; off; off >>= 1) s += __shfl_xor_sync(0xffffffffu, s, off);
        if (lane == 0) sqn[wid] = fmaxf(sqrtf(s), EPSV);
    }
    __syncthreads();

    // per-lane d1 weights
    float4 w0 = *(const float4*)(d1_w + lane*4);
    float4 w1 = *(const float4*)(d1_w + 128 + lane*4);
    float4 w2 = *(const float4*)(d1_w + 256 + lane*4);
    float4 db = *(const float4*)(d1_b + lane*4);

    const float* xb = xyz + (size_t)b*NPTS*3;

    // neighbor loop: warp handles j = it*8 + wid
#pragma unroll 1
    for (int it = 0; it < 8; it++) {
        int j   = it*8 + wid;                  // 0..63
        int row = j >> 4;                      // 0..3
        int n   = (m0 + row) & (NPTS - 1);
        int idx = sidx[j];

        float4 kf = *(const float4*)(g_kf + ((size_t)(b*NPTS + idx))*DMf + lane*4);
        float4 qf = *(const float4*)(Qs + row*128 + lane*4);
        float dq = qf.x*kf.x + qf.y*kf.y + qf.z*kf.z + qf.w*kf.w;
        float dk = kf.x*kf.x + kf.y*kf.y + kf.z*kf.z + kf.w*kf.w;
#pragma unroll
        for (int off = 16; off; off >>= 1) {
            dq += __shfl_xor_sync(0xffffffffu, dq, off);
            dk += __shfl_xor_sync(0xffffffffu, dk, off);
        }
        float kn = fmaxf(sqrtf(dk), EPSV);
        if (lane == 0) ssim[j] = dq / (sqn[row] * kn);

        *(float4*)(Bs + j*PITCH + lane*4) =
            make_float4(qf.x-kf.x, qf.y-kf.y, qf.z-kf.z, qf.w-kf.w);

        float cx = xb[n*3+0] - xb[idx*3+0];
        float cy = xb[n*3+1] - xb[idx*3+1];
        float cz = xb[n*3+2] - xb[idx*3+2];
        float4 h;
        h.x = fmaxf(cx*w0.x + cy*w1.x + cz*w2.x + db.x, 0.0f);
        h.y = fmaxf(cx*w0.y + cy*w1.y + cz*w2.y + db.y, 0.0f);
        h.z = fmaxf(cx*w0.z + cy*w1.z + cz*w2.z + db.z, 0.0f);
        h.w = fmaxf(cx*w0.w + cy*w1.w + cz*w2.w + db.w, 0.0f);
        *(float4*)(As + j*PITCH + lane*4) = h;
    }
    __syncthreads();

    // ---- 4-GEMM chain with ping-pong weight quarters ----
    const float* Wseq[4] = { d2_w, sim_w + 128, g1_w, g2_w };
    const float* tiles[4] = { As, Bs, As, Bs };
    unsigned long long acc[4][4];
    int ch = 0;

    for (int g = 0; g < 4; g++) {
        if (g != 1) {
#pragma unroll
            for (int i = 0; i < 4; i++)
#pragma unroll
                for (int j = 0; j < 4; j++) acc[i][j] = 0ULL;
        }
        for (int q = 0; q < 4; q++) {
            int nc = ch + 1;
            if (nc < 16) {
                loadq32(sW + (unsigned)((nc&1)*32*128)*4u, Wseq[nc>>2], nc&3, tid);
                cpa_commit();
                cpa_wait<1>();
            } else {
                cpa_wait<0>();
            }
            __syncthreads();
            mm32(tiles[g], q*32, Wb + (ch&1)*32*128, tm, tn, acc);
            __syncthreads();
            ch++;
        }

        if (g == 0) {
            // epi1: += d2_b; write pe; keep acc
            float4 b0 = *(const float4*)(d2_b + tn*4);
            float4 b1 = *(const float4*)(d2_b + 64 + tn*4);
            float bb[8] = {b0.x,b0.y,b0.z,b0.w,b1.x,b1.y,b1.z,b1.w};
#pragma unroll
            for (int i = 0; i < 4; i++) {
                size_t row = bm + tm*4 + i;
                float v[8];
#pragma unroll
                for (int j = 0; j < 4; j++) {
                    float2 f = unpack2(acc[i][j]);
                    v[2*j] = f.x + bb[2*j]; v[2*j+1] = f.y + bb[2*j+1];
                    acc[i][j] = pack2(v[2*j], v[2*j+1]);
                }
                *(float4*)(g_pe + row*128 + tn*4)      = make_float4(v[0],v[1],v[2],v[3]);
                *(float4*)(g_pe + row*128 + 64 + tn*4) = make_float4(v[4],v[5],v[6],v[7]);
            }
        } else if (g == 1) {
            // epi2: += sim_b + sim*sim_w[0]; stage t -> As
            float4 b0 = *(const float4*)(sim_b + tn*4);
            float4 b1 = *(const float4*)(sim_b + 64 + tn*4);
            float4 s0 = *(const float4*)(sim_w + tn*4);
            float4 s1 = *(const float4*)(sim_w + 64 + tn*4);
            float bb[8] = {b0.x,b0.y,b0.z,b0.w,b1.x,b1.y,b1.z,b1.w};
            float sw[8] = {s0.x,s0.y,s0.z,s0.w,s1.x,s1.y,s1.z,s1.w};
#pragma unroll
            for (int i = 0; i < 4; i++) {
                int r = tm*4 + i;
                float sv = ssim[r];
                float v[8];
#pragma unroll
                for (int j = 0; j < 4; j++) {
                    float2 f = unpack2(acc[i][j]);
                    v[2*j]   = f.x + bb[2*j]   + sv*sw[2*j];
                    v[2*j+1] = f.y + bb[2*j+1] + sv*sw[2*j+1];
                }
                *(float4*)(As + r*PITCH + tn*4)      = make_float4(v[0],v[1],v[2],v[3]);
                *(float4*)(As + r*PITCH + 64 + tn*4) = make_float4(v[4],v[5],v[6],v[7]);
            }
            __syncthreads();
        } else if (g == 2) {
            // epi3: relu(+g1_b); stage h2 -> Bs
            float4 b0 = *(const float4*)(g1_b + tn*4);
            float4 b1 = *(const float4*)(g1_b + 64 + tn*4);
            float bb[8] = {b0.x,b0.y,b0.z,b0.w,b1.x,b1.y,b1.z,b1.w};
#pragma unroll
            for (int i = 0; i < 4; i++) {
                int r = tm*4 + i;
                float v[8];
#pragma unroll
                for (int j = 0; j < 4; j++) {
                    float2 f = unpack2(acc[i][j]);
                    v[2*j]   = fmaxf(f.x + bb[2*j],   0.0f);
                    v[2*j+1] = fmaxf(f.y + bb[2*j+1], 0.0f);
                }
                *(float4*)(Bs + r*PITCH + tn*4)      = make_float4(v[0],v[1],v[2],v[3]);
                *(float4*)(Bs + r*PITCH + 64 + tn*4) = make_float4(v[4],v[5],v[6],v[7]);
            }
            __syncthreads();
        } else {
            // epi4: += g2_b; write logits
            float4 b0 = *(const float4*)(g2_b + tn*4);
            float4 b1 = *(const float4*)(g2_b + 64 + tn*4);
            float bb[8] = {b0.x,b0.y,b0.z,b0.w,b1.x,b1.y,b1.z,b1.w};
#pragma unroll
            for (int i = 0; i < 4; i++) {
                size_t row = bm + tm*4 + i;
                float v[8];
#pragma unroll
                for (int j = 0; j < 4; j++) {
                    float2 f = unpack2(acc[i][j]);
                    v[2*j] = f.x + bb[2*j]; v[2*j+1] = f.y + bb[2*j+1];
                }
                *(float4*)(g_logits + row*128 + tn*4)      = make_float4(v[0],v[1],v[2],v[3]);
                *(float4*)(g_logits + row*128 + 64 + tn*4) = make_float4(v[4],v[5],v[6],v[7]);
            }
        }
    }
}

// ---------------- stage F ----------------
__global__ void stage_f(const float* __restrict__ features,
                        const float* __restrict__ fc2_w,
                        const float* __restrict__ fc2_b,
                        float* __restrict__ out) {
    int row = blockIdx.x;
    int f = threadIdx.x;
    int b = row >> 12;
    const float scale = 1.0f / sqrtf(128.0f);

    float a[KNN];
    float mx = -3.4e38f;
#pragma unroll
    for (int k = 0; k < KNN; k++) {
        a[k] = g_logits[((size_t)row*KNN + k)*DMf + f] * scale;
        mx = fmaxf(mx, a[k]);
    }
    float sum = 0.0f;
#pragma unroll
    for (int k = 0; k < KNN; k++) { a[k] = expf(a[k] - mx); sum += a[k]; }
    float inv = 1.0f / sum;

    float* out_attn = out + (size_t)M1*DPf;
    float r = 0.0f;
#pragma unroll
    for (int k = 0; k < KNN; k++) {
        float at = a[k] * inv;
        size_t orow = ((size_t)row*KNN + k)*DMf;
        out_attn[orow + f] = at;
        int idx = g_idx[row*KNN + k];
        float v = g_vf[((size_t)(b*NPTS + idx))*DMf + f] + g_pe[orow + f];
        r += at * v;
    }
    __shared__ float rs[DMf];
    rs[f] = r;
    __syncthreads();
    if (f < DPf) {
        float o = fc2_b[f];
#pragma unroll 8
        for (int j = 0; j < DMf; j++) o += rs[j] * fc2_w[j*DPf + f];
        o += features[(size_t)row*DPf + f];
        out[(size_t)row*DPf + f] = o;
    }
}

// ---------------- launch ----------------
extern "C" void kernel_launch(void* const* d_in, const int* in_sizes, int n_in,
                              void* d_out, int out_size) {
    const float* xyz   = (const float*)d_in[0];
    const float* feat  = (const float*)d_in[1];
    const float* fc1_w = (const float*)d_in[2];
    const float* fc1_b = (const float*)d_in[3];
    const float* fc2_w = (const float*)d_in[4];
    const float* fc2_b = (const float*)d_in[5];
    const float* d1_w  = (const float*)d_in[6];
    const float* d1_b  = (const float*)d_in[7];
    const float* d2_w  = (const float*)d_in[8];
    const float* d2_b  = (const float*)d_in[9];
    const float* g1_w  = (const float*)d_in[10];
    const float* g1_b  = (const float*)d_in[11];
    const float* g2_w  = (const float*)d_in[12];
    const float* g2_b  = (const float*)d_in[13];
    const float* wq_w  = (const float*)d_in[14];
    const float* wk_w  = (const float*)d_in[15];
    const float* wv_w  = (const float*)d_in[16];
    const float* sim_w = (const float*)d_in[17];
    const float* sim_b = (const float*)d_in[18];
    float* out = (float*)d_out;

    static float *p_x = nullptr, *p_q, *p_kf, *p_vf;
    static bool attr_done = false;
    const int FUSED_SMEM = FUSED_FLOATS * 4;   // 102928 B
    if (!attr_done) {
        cudaGetSymbolAddress((void**)&p_x,  g_x);
        cudaGetSymbolAddress((void**)&p_q,  g_q);
        cudaGetSymbolAddress((void**)&p_kf, g_kf);
        cudaGetSymbolAddress((void**)&p_vf, g_vf);
        cudaFuncSetAttribute(fused_chain,
                             cudaFuncAttributeMaxDynamicSharedMemorySize, FUSED_SMEM);
        attr_done = true;
    }

    // 0) KNN
    knn_kernel<<<M1/4, 128>>>(xyz);

    // 1) x = features @ fc1 + b
    gemm_small<<<M1/128, 256>>>(feat, DPf, DPf, fc1_w, fc1_b, p_x,
                                nullptr, nullptr, nullptr, nullptr);

    // 2) q, k, v (batched)
    gemm_small<<<dim3(M1/128, 3), 256>>>(p_x, DMf, DMf, wq_w, nullptr, p_q,
                                         wk_w, p_kf, wv_w, p_vf);

    // 3) fused: gather + sim + h1/qk + pe + t + h2 + logits
    fused_chain<<<M2/BROWS, 256, FUSED_SMEM>>>(xyz, d1_w, d1_b,
                                               d2_w, d2_b, sim_w, sim_b,
                                               g1_w, g1_b, g2_w, g2_b);

    // 4) softmax + weighted sum + fc2 + residual
    stage_f<<<M1, 128>>>(feat, fc2_w, fc2_b, out);
}

// round 7
// speedup vs baseline: 2.0221x; 2.0221x over previous
#include <cuda_runtime.h>
#include <math.h>

#define NB 4
#define NPTS 4096
#define KNN 16
#define DPf 64
#define DMf 128
#define M1 (NB*NPTS)          /* 16384  */
#define M2 (M1*KNN)           /* 262144 */
#define EPSV 1e-8f
#define PITCH 132             /* smem row pitch (floats); 4*132=528, %32=16 -> conflict-free */
#define BROWS 64              /* rows per fused CTA */

// ---------------- scratch ----------------
__device__ float g_x [(size_t)M1*DMf];
__device__ float g_q [(size_t)M1*DMf];
__device__ float g_kf[(size_t)M1*DMf];
__device__ float g_vf[(size_t)M1*DMf];
__device__ int   g_idx[M1*KNN];
__device__ float g_sim[M2];
__device__ float g_bufA[(size_t)M2*DMf];   // h1 -> logits
__device__ float g_bufB[(size_t)M2*DMf];   // qk -> h2 (smem-staged)
__device__ float g_pe  [(size_t)M2*DMf];   // pos_enc

// ---------------- packed f32x2 helpers ----------------
__device__ __forceinline__ unsigned long long pack2(float x, float y) {
    unsigned long long r;
    asm("mov.b64 %0, {%1, %2};" : "=l"(r) : "f"(x), "f"(y));
    return r;
}
__device__ __forceinline__ float2 unpack2(unsigned long long v) {
    float2 f;
    asm("mov.b64 {%0, %1}, %2;" : "=f"(f.x), "=f"(f.y) : "l"(v));
    return f;
}
__device__ __forceinline__ void ffma2(unsigned long long& d,
                                      unsigned long long a,
                                      unsigned long long b) {
    asm("fma.rn.f32x2 %0, %1, %2, %0;" : "+l"(d) : "l"(a), "l"(b));
}

// ---------------- cp.async helpers ----------------
__device__ __forceinline__ unsigned smem_u32(const void* p) {
    unsigned a;
    asm("{ .reg .u64 t; cvta.to.shared.u64 t, %1; cvt.u32.u64 %0, t; }" : "=r"(a) : "l"(p));
    return a;
}
__device__ __forceinline__ void cpa16(unsigned dst, const void* src) {
    asm volatile("cp.async.ca.shared.global [%0], [%1], 16;" :: "r"(dst), "l"(src));
}
__device__ __forceinline__ void cpa_commit() { asm volatile("cp.async.commit_group;"); }
template<int N> __device__ __forceinline__ void cpa_wait() {
    asm volatile("cp.async.wait_group %0;" :: "n"(N));
}

// ---------------- KNN: warp per query, BRANCHLESS static-register top-16 ----------------
__global__ void knn_kernel(const float* __restrict__ xyz) {
    int warp = threadIdx.x >> 5;
    int lane = threadIdx.x & 31;
    int row  = blockIdx.x * 4 + warp;
    int b = row >> 12;
    int n = row & (NPTS - 1);
    const float* xb = xyz + (size_t)b * NPTS * 3;
    float qx = xb[n*3+0], qy = xb[n*3+1], qz = xb[n*3+2];
    float sq = qx*qx + qy*qy + qz*qz;

    // sorted ascending; keys are unique ((dist_map<<32)|idx), so strict < is exact.
    unsigned long long best[16];
#pragma unroll
    for (int i = 0; i < 16; i++) best[i] = ~0ULL;

    for (int t = 0; t < NPTS/32; t++) {
        int j = t*32 + lane;
        float x = xb[j*3+0], y = xb[j*3+1], z = xb[j*3+2];
        float sj = x*x + y*y + z*z;
        float d = sq + sj - 2.0f*(qx*x + qy*y + qz*z);   // exact reference formula
        unsigned u = __float_as_uint(d);
        u = (u & 0x80000000u) ? ~u : (u | 0x80000000u);  // order-preserving map
        unsigned long long key = ((unsigned long long)u << 32) | (unsigned)j;

        // branchless sorted insert, all static indices -> stays in registers
        bool pi = key < best[15];
#pragma unroll
        for (int i = 15; i >= 1; i--) {
            bool pim = key < best[i-1];
            best[i] = pi ? (pim ? best[i-1] : key) : best[i];
            pi = pim;
        }
        best[0] = pi ? key : best[0];
    }

    __shared__ unsigned long long sh[4][512];
#pragma unroll
    for (int i = 0; i < 16; i++) sh[warp][lane*16 + i] = best[i];
    __syncwarp();

    int p = 0;
    for (int r = 0; r < 16; r++) {
        unsigned long long v = (p < 16) ? sh[warp][lane*16 + p] : ~0ULL;
        unsigned long long m = v;
#pragma unroll
        for (int off = 16; off; off >>= 1) {
            unsigned long long o = __shfl_xor_sync(0xffffffffu, m, off);
            m = (o < m) ? o : m;
        }
        if (v == m) { g_idx[row*KNN + r] = (int)(m & 0xffffffffu); p++; }
        __syncwarp();
    }
}

// ---------------- small fp32 GEMM (fc1, qkv) ----------------
__global__ void __launch_bounds__(256, 2)
gemm_small(const float* __restrict__ A, int lda, int Ka,
           const float* __restrict__ W,
           const float* __restrict__ bias,
           float* __restrict__ C,
           const float* W2, float* C2, const float* W3, float* C3) {
    __shared__ float As[32][132];
    __shared__ float Ws[32][128];

    if (gridDim.y == 3) {
        if (blockIdx.y == 1) { W = W2; C = C2; }
        else if (blockIdx.y == 2) { W = W3; C = C3; }
    }

    int bm  = blockIdx.x * 128;
    int tid = threadIdx.x;
    int tm  = tid >> 4, tn = tid & 15;

    unsigned long long acc[8][4];
#pragma unroll
    for (int i = 0; i < 8; i++)
#pragma unroll
        for (int j = 0; j < 4; j++) acc[i][j] = 0ULL;

    for (int k0 = 0; k0 < Ka; k0 += 32) {
#pragma unroll
        for (int pss = 0; pss < 4; pss++) {
            int idx4 = pss*256 + tid;
            int r  = idx4 >> 3;
            int c4 = idx4 & 7;
            float4 v = *(const float4*)(A + (size_t)(bm + r)*lda + k0 + c4*4);
            As[c4*4+0][r] = v.x; As[c4*4+1][r] = v.y;
            As[c4*4+2][r] = v.z; As[c4*4+3][r] = v.w;
        }
#pragma unroll
        for (int pss = 0; pss < 4; pss++) {
            int idx4 = pss*256 + tid;
            int r  = idx4 >> 5;
            int c4 = idx4 & 31;
            *(float4*)&Ws[r][c4*4] = *(const float4*)(W + (size_t)(k0 + r)*128 + c4*4);
        }
        __syncthreads();
#pragma unroll
        for (int kk = 0; kk < 32; kk++) {
            float4 a0 = *(const float4*)&As[kk][tm*8];
            float4 a1 = *(const float4*)&As[kk][tm*8 + 4];
            unsigned long long bv[4];
            bv[0] = *(const unsigned long long*)&Ws[kk][tn*8];
            bv[1] = *(const unsigned long long*)&Ws[kk][tn*8+2];
            bv[2] = *(const unsigned long long*)&Ws[kk][tn*8+4];
            bv[3] = *(const unsigned long long*)&Ws[kk][tn*8+6];
            unsigned long long av[8] = { pack2(a0.x, a0.x), pack2(a0.y, a0.y),
                                         pack2(a0.z, a0.z), pack2(a0.w, a0.w),
                                         pack2(a1.x, a1.x), pack2(a1.y, a1.y),
                                         pack2(a1.z, a1.z), pack2(a1.w, a1.w) };
#pragma unroll
            for (int i = 0; i < 8; i++)
#pragma unroll
                for (int j = 0; j < 4; j++) ffma2(acc[i][j], av[i], bv[j]);
        }
        __syncthreads();
    }

    float bia[8];
#pragma unroll
    for (int j = 0; j < 8; j++) bia[j] = bias ? bias[tn*8 + j] : 0.0f;

#pragma unroll
    for (int i = 0; i < 8; i++) {
        size_t row = (size_t)bm + tm*8 + i;
        float v[8];
#pragma unroll
        for (int j = 0; j < 4; j++) {
            float2 f = unpack2(acc[i][j]);
            v[2*j]   = f.x + bia[2*j];
            v[2*j+1] = f.y + bia[2*j+1];
        }
        float4* cp = (float4*)(C + row*128 + tn*8);
        cp[0] = make_float4(v[0], v[1], v[2], v[3]);
        cp[1] = make_float4(v[4], v[5], v[6], v[7]);
    }
}

// ---------------- fused chain (R5 v2 structure): 64-row blocks, 2 CTAs/SM ----------------
__device__ __forceinline__ void gemm_inner64(const float* __restrict__ Asm, int kbase,
                                             const float* __restrict__ Wsm,
                                             int tm, int tn,
                                             unsigned long long acc[4][4]) {
    const float* ap = Asm + tm*4*PITCH + kbase;
#pragma unroll 8
    for (int kk = 0; kk < 64; kk++) {
        unsigned long long b0 = *(const unsigned long long*)&Wsm[kk*128 + tn*4];
        unsigned long long b1 = *(const unsigned long long*)&Wsm[kk*128 + tn*4 + 2];
        unsigned long long b2 = *(const unsigned long long*)&Wsm[kk*128 + 64 + tn*4];
        unsigned long long b3 = *(const unsigned long long*)&Wsm[kk*128 + 64 + tn*4 + 2];
#pragma unroll
        for (int i = 0; i < 4; i++) {
            float a = ap[i*PITCH + kk];
            unsigned long long av = pack2(a, a);
            ffma2(acc[i][0], av, b0);
            ffma2(acc[i][1], av, b1);
            ffma2(acc[i][2], av, b2);
            ffma2(acc[i][3], av, b3);
        }
    }
}

__device__ __forceinline__ void load_tile_async(unsigned sT, const float* __restrict__ G,
                                                size_t bm, int tid) {
#pragma unroll
    for (int it = 0; it < 8; it++) {
        int c = it*256 + tid;
        int r = c >> 5, k = c & 31;
        cpa16(sT + (unsigned)(r*PITCH + k*4)*4u, G + (bm + r)*128 + k*4);
    }
}
__device__ __forceinline__ void load_W_half(unsigned sW, const float* __restrict__ W, int h, int tid) {
    const float* src = W + (size_t)h*64*128;
#pragma unroll
    for (int it = 0; it < 8; it++) {
        int c = it*256 + tid;
        cpa16(sW + (unsigned)c*16u, src + c*4);
    }
}

__global__ void __launch_bounds__(256, 2)
fused_chain(const float* __restrict__ d2_w, const float* __restrict__ d2_b,
            const float* __restrict__ sim_w, const float* __restrict__ sim_b,
            const float* __restrict__ g1_w, const float* __restrict__ g1_b,
            const float* __restrict__ g2_w, const float* __restrict__ g2_b) {
    extern __shared__ float sm[];
    float* As = sm;
    float* Bs = sm + BROWS*PITCH;
    float* Ws = sm + 2*BROWS*PITCH;
    unsigned sAs = smem_u32(As), sBs = smem_u32(Bs), sWs = smem_u32(Ws);

    int tid = threadIdx.x;
    int tm = tid >> 4, tn = tid & 15;
    size_t bm = (size_t)blockIdx.x * BROWS;

    load_tile_async(sAs, g_bufA, bm, tid);
    load_W_half(sWs, d2_w, 0, tid);
    cpa_commit();
    load_tile_async(sBs, g_bufB, bm, tid);
    cpa_commit();
    cpa_wait<1>();
    __syncthreads();

    unsigned long long acc[4][4];
#pragma unroll
    for (int i = 0; i < 4; i++)
#pragma unroll
        for (int j = 0; j < 4; j++) acc[i][j] = 0ULL;

#define RELOAD_W(Wp, h)  do { __syncthreads(); load_W_half(sWs, (Wp), (h), tid); \
                              cpa_commit(); cpa_wait<0>(); __syncthreads(); } while (0)

    // ---- GEMM1: acc = h1 @ d2 ----
    gemm_inner64(As, 0, Ws, tm, tn, acc);
    RELOAD_W(d2_w, 1);
    gemm_inner64(As, 64, Ws, tm, tn, acc);

    {   // epi1
        float4 b0 = *(const float4*)(d2_b + tn*4);
        float4 b1 = *(const float4*)(d2_b + 64 + tn*4);
        float bb[8] = {b0.x,b0.y,b0.z,b0.w,b1.x,b1.y,b1.z,b1.w};
#pragma unroll
        for (int i = 0; i < 4; i++) {
            size_t row = bm + tm*4 + i;
            float v[8];
#pragma unroll
            for (int j = 0; j < 4; j++) {
                float2 f = unpack2(acc[i][j]);
                v[2*j] = f.x + bb[2*j]; v[2*j+1] = f.y + bb[2*j+1];
                acc[i][j] = pack2(v[2*j], v[2*j+1]);
            }
            *(float4*)(g_pe + row*128 + tn*4)      = make_float4(v[0],v[1],v[2],v[3]);
            *(float4*)(g_pe + row*128 + 64 + tn*4) = make_float4(v[4],v[5],v[6],v[7]);
        }
    }

    // ---- GEMM2: acc += qk @ simw' ----
    RELOAD_W(sim_w + 128, 0);
    gemm_inner64(Bs, 0, Ws, tm, tn, acc);
    RELOAD_W(sim_w + 128, 1);
    gemm_inner64(Bs, 64, Ws, tm, tn, acc);

    {   // epi2 -> stage t in As
        float4 b0 = *(const float4*)(sim_b + tn*4);
        float4 b1 = *(const float4*)(sim_b + 64 + tn*4);
        float4 s0 = *(const float4*)(sim_w + tn*4);
        float4 s1 = *(const float4*)(sim_w + 64 + tn*4);
        float bb[8] = {b0.x,b0.y,b0.z,b0.w,b1.x,b1.y,b1.z,b1.w};
        float sw[8] = {s0.x,s0.y,s0.z,s0.w,s1.x,s1.y,s1.z,s1.w};
#pragma unroll
        for (int i = 0; i < 4; i++) {
            int r = tm*4 + i;
            float sv = g_sim[bm + r];
            float v[8];
#pragma unroll
            for (int j = 0; j < 4; j++) {
                float2 f = unpack2(acc[i][j]);
                v[2*j]   = f.x + bb[2*j]   + sv*sw[2*j];
                v[2*j+1] = f.y + bb[2*j+1] + sv*sw[2*j+1];
            }
            *(float4*)&As[r*PITCH + tn*4]      = make_float4(v[0],v[1],v[2],v[3]);
            *(float4*)&As[r*PITCH + 64 + tn*4] = make_float4(v[4],v[5],v[6],v[7]);
        }
    }

    // ---- GEMM3: acc = t @ g1 ----
#pragma unroll
    for (int i = 0; i < 4; i++)
#pragma unroll
        for (int j = 0; j < 4; j++) acc[i][j] = 0ULL;
    RELOAD_W(g1_w, 0);
    gemm_inner64(As, 0, Ws, tm, tn, acc);
    RELOAD_W(g1_w, 1);
    gemm_inner64(As, 64, Ws, tm, tn, acc);

    {   // epi3 -> stage h2 in Bs
        float4 b0 = *(const float4*)(g1_b + tn*4);
        float4 b1 = *(const float4*)(g1_b + 64 + tn*4);
        float bb[8] = {b0.x,b0.y,b0.z,b0.w,b1.x,b1.y,b1.z,b1.w};
#pragma unroll
        for (int i = 0; i < 4; i++) {
            int r = tm*4 + i;
            float v[8];
#pragma unroll
            for (int j = 0; j < 4; j++) {
                float2 f = unpack2(acc[i][j]);
                v[2*j]   = fmaxf(f.x + bb[2*j],   0.0f);
                v[2*j+1] = fmaxf(f.y + bb[2*j+1], 0.0f);
            }
            *(float4*)&Bs[r*PITCH + tn*4]      = make_float4(v[0],v[1],v[2],v[3]);
            *(float4*)&Bs[r*PITCH + 64 + tn*4] = make_float4(v[4],v[5],v[6],v[7]);
        }
    }

    // ---- GEMM4: acc = h2 @ g2 ----
#pragma unroll
    for (int i = 0; i < 4; i++)
#pragma unroll
        for (int j = 0; j < 4; j++) acc[i][j] = 0ULL;
    RELOAD_W(g2_w, 0);
    gemm_inner64(Bs, 0, Ws, tm, tn, acc);
    RELOAD_W(g2_w, 1);
    gemm_inner64(Bs, 64, Ws, tm, tn, acc);

    {   // epi4 -> logits
        float4 b0 = *(const float4*)(g2_b + tn*4);
        float4 b1 = *(const float4*)(g2_b + 64 + tn*4);
        float bb[8] = {b0.x,b0.y,b0.z,b0.w,b1.x,b1.y,b1.z,b1.w};
#pragma unroll
        for (int i = 0; i < 4; i++) {
            size_t row = bm + tm*4 + i;
            float v[8];
#pragma unroll
            for (int j = 0; j < 4; j++) {
                float2 f = unpack2(acc[i][j]);
                v[2*j] = f.x + bb[2*j]; v[2*j+1] = f.y + bb[2*j+1];
            }
            *(float4*)(g_bufA + row*128 + tn*4)      = make_float4(v[0],v[1],v[2],v[3]);
            *(float4*)(g_bufA + row*128 + 64 + tn*4) = make_float4(v[4],v[5],v[6],v[7]);
        }
    }
#undef RELOAD_W
}

// ---------------- stage D: warp per row, shfl reductions ----------------
__global__ void stage_d(const float* __restrict__ xyz,
                        const float* __restrict__ d1_w,
                        const float* __restrict__ d1_b) {
    int wid = threadIdx.x >> 5, lane = threadIdx.x & 31;
    int row = blockIdx.x * 8 + wid;
    int b = row >> 12;
    int n = row & (NPTS - 1);
    const float* xb = xyz + (size_t)b*NPTS*3;
    float qx = xb[n*3+0], qy = xb[n*3+1], qz = xb[n*3+2];

    float4 qf = *(const float4*)(g_q + (size_t)row*DMf + lane*4);
    float s = qf.x*qf.x + qf.y*qf.y + qf.z*qf.z + qf.w*qf.w;
#pragma unroll
    for (int off = 16; off; off >>= 1) s += __shfl_xor_sync(0xffffffffu, s, off);
    float qn = fmaxf(sqrtf(s), EPSV);

    float4 w0 = *(const float4*)(d1_w + lane*4);
    float4 w1 = *(const float4*)(d1_w + 128 + lane*4);
    float4 w2 = *(const float4*)(d1_w + 256 + lane*4);
    float4 db = *(const float4*)(d1_b + lane*4);

#pragma unroll 2
    for (int k = 0; k < KNN; k++) {
        int idx = g_idx[row*KNN + k];
        const float* kp = g_kf + ((size_t)(b*NPTS + idx))*DMf + lane*4;
        float4 kf = *(const float4*)kp;
        float dq = qf.x*kf.x + qf.y*kf.y + qf.z*kf.z + qf.w*kf.w;
        float dk = kf.x*kf.x + kf.y*kf.y + kf.z*kf.z + kf.w*kf.w;
#pragma unroll
        for (int off = 16; off; off >>= 1) {
            dq += __shfl_xor_sync(0xffffffffu, dq, off);
            dk += __shfl_xor_sync(0xffffffffu, dk, off);
        }
        float kn = fmaxf(sqrtf(dk), EPSV);
        float sim = dq / (qn * kn);
        if (lane == 0) g_sim[row*KNN + k] = sim;
        size_t orow = ((size_t)row*KNN + k)*DMf;
        *(float4*)(g_bufB + orow + lane*4) =
            make_float4(qf.x-kf.x, qf.y-kf.y, qf.z-kf.z, qf.w-kf.w);
        float cx = qx - xb[idx*3+0];
        float cy = qy - xb[idx*3+1];
        float cz = qz - xb[idx*3+2];
        float4 h;
        h.x = fmaxf(cx*w0.x + cy*w1.x + cz*w2.x + db.x, 0.0f);
        h.y = fmaxf(cx*w0.y + cy*w1.y + cz*w2.y + db.y, 0.0f);
        h.z = fmaxf(cx*w0.z + cy*w1.z + cz*w2.z + db.z, 0.0f);
        h.w = fmaxf(cx*w0.w + cy*w1.w + cz*w2.w + db.w, 0.0f);
        *(float4*)(g_bufA + orow + lane*4) = h;
    }
}

// ---------------- stage F ----------------
__global__ void stage_f(const float* __restrict__ features,
                        const float* __restrict__ fc2_w,
                        const float* __restrict__ fc2_b,
                        float* __restrict__ out) {
    int row = blockIdx.x;
    int f = threadIdx.x;
    int b = row >> 12;
    const float scale = 1.0f / sqrtf(128.0f);

    float a[KNN];
    float mx = -3.4e38f;
#pragma unroll
    for (int k = 0; k < KNN; k++) {
        a[k] = g_bufA[((size_t)row*KNN + k)*DMf + f] * scale;
        mx = fmaxf(mx, a[k]);
    }
    float sum = 0.0f;
#pragma unroll
    for (int k = 0; k < KNN; k++) { a[k] = expf(a[k] - mx); sum += a[k]; }
    float inv = 1.0f / sum;

    float* out_attn = out + (size_t)M1*DPf;
    float r = 0.0f;
#pragma unroll
    for (int k = 0; k < KNN; k++) {
        float at = a[k] * inv;
        size_t orow = ((size_t)row*KNN + k)*DMf;
        out_attn[orow + f] = at;
        int idx = g_idx[row*KNN + k];
        float v = g_vf[((size_t)(b*NPTS + idx))*DMf + f] + g_pe[orow + f];
        r += at * v;
    }
    __shared__ float rs[DMf];
    rs[f] = r;
    __syncthreads();
    if (f < DPf) {
        float o = fc2_b[f];
#pragma unroll 8
        for (int j = 0; j < DMf; j++) o += rs[j] * fc2_w[j*DPf + f];
        o += features[(size_t)row*DPf + f];
        out[(size_t)row*DPf + f] = o;
    }
}

// ---------------- launch ----------------
extern "C" void kernel_launch(void* const* d_in, const int* in_sizes, int n_in,
                              void* d_out, int out_size) {
    const float* xyz   = (const float*)d_in[0];
    const float* feat  = (const float*)d_in[1];
    const float* fc1_w = (const float*)d_in[2];
    const float* fc1_b = (const float*)d_in[3];
    const float* fc2_w = (const float*)d_in[4];
    const float* fc2_b = (const float*)d_in[5];
    const float* d1_w  = (const float*)d_in[6];
    const float* d1_b  = (const float*)d_in[7];
    const float* d2_w  = (const float*)d_in[8];
    const float* d2_b  = (const float*)d_in[9];
    const float* g1_w  = (const float*)d_in[10];
    const float* g1_b  = (const float*)d_in[11];
    const float* g2_w  = (const float*)d_in[12];
    const float* g2_b  = (const float*)d_in[13];
    const float* wq_w  = (const float*)d_in[14];
    const float* wk_w  = (const float*)d_in[15];
    const float* wv_w  = (const float*)d_in[16];
    const float* sim_w = (const float*)d_in[17];
    const float* sim_b = (const float*)d_in[18];
    float* out = (float*)d_out;

    static float *p_x = nullptr, *p_q, *p_kf, *p_vf;
    static bool attr_done = false;
    const int FUSED_SMEM = (2*BROWS*PITCH + BROWS*128) * 4;   // 100352 B
    if (!attr_done) {
        cudaGetSymbolAddress((void**)&p_x,  g_x);
        cudaGetSymbolAddress((void**)&p_q,  g_q);
        cudaGetSymbolAddress((void**)&p_kf, g_kf);
        cudaGetSymbolAddress((void**)&p_vf, g_vf);
        cudaFuncSetAttribute(fused_chain,
                             cudaFuncAttributeMaxDynamicSharedMemorySize, FUSED_SMEM);
        attr_done = true;
    }

    // 1) KNN (branchless register top-16)
    knn_kernel<<<M1/4, 128>>>(xyz);

    // 2) x = features @ fc1 + b
    gemm_small<<<M1/128, 256>>>(feat, DPf, DPf, fc1_w, fc1_b, p_x,
                                nullptr, nullptr, nullptr, nullptr);

    // 3) q, k, v (batched)
    gemm_small<<<dim3(M1/128, 3), 256>>>(p_x, DMf, DMf, wq_w, nullptr, p_q,
                                         wk_w, p_kf, wv_w, p_vf);

    // 4) gather + sim + (q-k)->bufB + pos-enc hidden->bufA
    stage_d<<<M1/8, 256>>>(xyz, d1_w, d1_b);

    // 5-8) fused GEMM chain
    fused_chain<<<M2/BROWS, 256, FUSED_SMEM>>>(d2_w, d2_b, sim_w, sim_b,
                                               g1_w, g1_b, g2_w, g2_b);

    // 9) softmax + weighted sum + fc2 + residual
    stage_f<<<M1, 128>>>(feat, fc2_w, fc2_b, out);
}